// round 4
// baseline (speedup 1.0000x reference)
#include <cuda_runtime.h>

// Problem constants (from reference)
#define S_TOK 131072
#define DIM   512
#define VOCAB 100000

// Scratch (device globals — zero at module load; finalize restores zeros).
__device__ int g_counts[VOCAB];   // tokens per vocab row (final histogram)
__device__ int g_nf;              // # designated (rank-0) tokens == # touched rows
__device__ int g_nr;              // # remaining tokens (rank >= 1)
__device__ int g_ftok[S_TOK];     // designated token index per touched row
__device__ int g_fvid[S_TOK];     // its vocab id
__device__ int g_rtok[S_TOK];     // remaining tokens
__device__ int g_rvid[S_TOK];

// ---------------------------------------------------------------------------
// Kernel 1: compact masked tokens into (first, rest) lists + histogram.
// The token whose atomicAdd returns 0 is the row's designated writer.
// ---------------------------------------------------------------------------
__global__ void compact_kernel(const int* __restrict__ l2_data,
                               const int* __restrict__ l2_idxs) {
    int i = blockIdx.x * blockDim.x + threadIdx.x;
    if (i >= S_TOK) return;
    if (l2_idxs[i] == 1) {
        int v = l2_data[i];
        int rank = atomicAdd(&g_counts[v], 1);
        if (rank == 0) {
            int pos = atomicAdd(&g_nf, 1);
            g_ftok[pos] = i;
            g_fvid[pos] = v;
        } else {
            int pos = atomicAdd(&g_nr, 1);
            g_rtok[pos] = i;
            g_rvid[pos] = v;
        }
    }
}

// ---------------------------------------------------------------------------
// Kernel 2: store pass over designated tokens. One warp per row, grid-stride.
//   c==1  -> final EMA:  out_row = 0.5*w + 0.5*x         (skipped in finalize)
//   c>=2  -> seed sums:  out_row = c*w + x               (atomics add the rest;
//            finalize scales by 0.5/c -> 0.5*w + 0.5*mean)
// Plain 16B stores, no atomics, no separate zero/init pass.
// ---------------------------------------------------------------------------
__global__ void store_kernel(const float4* __restrict__ out4,
                             const float4* __restrict__ w4,
                             float4* __restrict__ sums4) {
    int warp0  = (blockIdx.x * blockDim.x + threadIdx.x) >> 5;
    int nwarps = (gridDim.x * blockDim.x) >> 5;
    int lane   = threadIdx.x & 31;
    int n      = g_nf;

    for (int j = warp0; j < n; j += nwarps) {
        int tok = g_ftok[j];
        int v   = g_fvid[j];
        int cnt = g_counts[v];

        const float4* src = out4 + (long)tok * (DIM / 4);
        long vbase = (long)v * (DIM / 4);

        if (cnt == 1) {
#pragma unroll
            for (int i = 0; i < 4; i++) {
                int c = lane + i * 32;
                float4 x  = src[c];
                float4 wv = w4[vbase + c];
                sums4[vbase + c] = make_float4(
                    0.5f * (wv.x + x.x), 0.5f * (wv.y + x.y),
                    0.5f * (wv.z + x.z), 0.5f * (wv.w + x.w));
            }
        } else {
            float cf = (float)cnt;
#pragma unroll
            for (int i = 0; i < 4; i++) {
                int c = lane + i * 32;
                float4 x  = src[c];
                float4 wv = w4[vbase + c];
                sums4[vbase + c] = make_float4(
                    fmaf(cf, wv.x, x.x), fmaf(cf, wv.y, x.y),
                    fmaf(cf, wv.z, x.z), fmaf(cf, wv.w, x.w));
            }
        }
    }
}

// ---------------------------------------------------------------------------
// Kernel 3: atomic pass over remaining (rank>=1) tokens. Runs after the store
// pass (stream order), so the seed value is already in place.
// ---------------------------------------------------------------------------
__global__ void atomic_kernel(const float4* __restrict__ out4,
                              float* __restrict__ sums) {
    int warp0  = (blockIdx.x * blockDim.x + threadIdx.x) >> 5;
    int nwarps = (gridDim.x * blockDim.x) >> 5;
    int lane   = threadIdx.x & 31;
    int n      = g_nr;

    for (int j = warp0; j < n; j += nwarps) {
        int tok = g_rtok[j];
        int v   = g_rvid[j];
        const float4* src = out4 + (long)tok * (DIM / 4);
        float4* dst = (float4*)(sums + (long)v * DIM);
#pragma unroll
        for (int i = 0; i < 4; i++) {
            int c = lane + i * 32;
            float4 x = src[c];
            asm volatile(
                "red.global.add.v4.f32 [%0], {%1, %2, %3, %4};"
                :: "l"(dst + c), "f"(x.x), "f"(x.y), "f"(x.z), "f"(x.w)
                : "memory");
        }
    }
}

// ---------------------------------------------------------------------------
// Kernel 4: finalize + scratch reset.
//   c==0 -> out = w (copy)
//   c==1 -> already final (store pass), skip write
//   c>=2 -> out = sums * (0.5/c)       (sums = c*w + Sum(x))
// Then zero g_counts (each row's count is consumed only inside one block;
// __syncthreads orders reads before the zeroing store) and the counters.
// Grid is exact: VOCAB*DIM/4 / 256 = 50000 full blocks, no bounds checks.
// ---------------------------------------------------------------------------
__global__ void finalize_kernel(const float4* __restrict__ w4,
                                float4* __restrict__ out4) {
    long i = (long)blockIdx.x * blockDim.x + threadIdx.x;
    int row = (int)(i >> 7);            // i / 128 ; 2 rows per 256-thr block
    int c = g_counts[row];

    __syncthreads();                    // all reads of counts[row] done
    if ((i & 127) == 0) g_counts[row] = 0;
    if (i == 0) { g_nf = 0; g_nr = 0; }

    if (c == 1) return;                 // uniform per-row -> no divergence

    float4 o;
    if (c == 0) {
        o = w4[i];
    } else {
        float4 s = out4[i];
        float inv = 0.5f / (float)c;
        o = make_float4(s.x * inv, s.y * inv, s.z * inv, s.w * inv);
    }
    out4[i] = o;
}

// ---------------------------------------------------------------------------
extern "C" void kernel_launch(void* const* d_in, const int* in_sizes, int n_in,
                              void* d_out, int out_size) {
    const float* out_act   = (const float*)d_in[0];   // [S, D] f32
    const float* l2_weight = (const float*)d_in[1];   // [V, D] f32
    const int*   l2_data   = (const int*)d_in[2];     // [S] i32
    const int*   l2_idxs   = (const int*)d_in[3];     // [S] i32
    float* outp = (float*)d_out;                      // [V, D] f32

    (void)in_sizes; (void)n_in; (void)out_size;

    // 1. compact (counts are zero on entry: module-load zero / finalize reset)
    compact_kernel<<<S_TOK / 256, 256>>>(l2_data, l2_idxs);

    // 2. store pass: designated token per touched row, plain stores
    store_kernel<<<2048, 256>>>((const float4*)out_act,
                                (const float4*)l2_weight,
                                (float4*)outp);

    // 3. atomic pass: remaining tokens
    atomic_kernel<<<1024, 256>>>((const float4*)out_act, outp);

    // 4. finalize + scratch reset (exact grid: 50000 blocks)
    finalize_kernel<<<(VOCAB * (DIM / 4)) / 256, 256>>>(
        (const float4*)l2_weight, (float4*)outp);
}

// round 5
// speedup vs baseline: 1.2801x; 1.2801x over previous
#include <cuda_runtime.h>

// Problem constants (from reference)
#define S_TOK 131072
#define DIM   512
#define VOCAB 100000

// Scratch (device globals — no runtime allocation allowed).
__device__ int g_counts[VOCAB];   // tokens per vocab row (final histogram)
__device__ int g_nf;              // # designated (rank-0) tokens == # touched rows
__device__ int g_nr;              // # remaining tokens (rank >= 1)
__device__ int g_ftok[S_TOK];     // designated token index per touched row
__device__ int g_fvid[S_TOK];     // its vocab id
__device__ int g_rtok[S_TOK];     // remaining tokens
__device__ int g_rvid[S_TOK];

// ---------------------------------------------------------------------------
// Kernel 0: zero counts + counters (cheap: 391 blocks)
// ---------------------------------------------------------------------------
__global__ void zero_counts_kernel() {
    int i = blockIdx.x * blockDim.x + threadIdx.x;
    if (i < VOCAB) g_counts[i] = 0;
    if (i == 0) { g_nf = 0; g_nr = 0; }
}

// ---------------------------------------------------------------------------
// Kernel 1: compact masked tokens into (first, rest) lists + histogram.
// The token whose atomicAdd returns 0 is the row's designated writer.
// ---------------------------------------------------------------------------
__global__ void compact_kernel(const int* __restrict__ l2_data,
                               const int* __restrict__ l2_idxs) {
    int i = blockIdx.x * blockDim.x + threadIdx.x;
    if (i >= S_TOK) return;
    if (l2_idxs[i] == 1) {
        int v = l2_data[i];
        int rank = atomicAdd(&g_counts[v], 1);
        if (rank == 0) {
            int pos = atomicAdd(&g_nf, 1);
            g_ftok[pos] = i;
            g_fvid[pos] = v;
        } else {
            int pos = atomicAdd(&g_nr, 1);
            g_rtok[pos] = i;
            g_rvid[pos] = v;
        }
    }
}

// ---------------------------------------------------------------------------
// Kernel 2: store pass over designated tokens. One warp per row, grid-stride.
//   c==1  -> final EMA:  out_row = 0.5*w + 0.5*x         (skipped in finalize)
//   c>=2  -> seed sums:  out_row = c*w + x               (atomics add the rest;
//            finalize scales by 0.5/c -> 0.5*w + 0.5*mean)
// Plain 16B stores, no atomics, no separate zero/init pass.
// ---------------------------------------------------------------------------
__global__ void store_kernel(const float4* __restrict__ out4,
                             const float4* __restrict__ w4,
                             float4* __restrict__ sums4) {
    int warp0  = (blockIdx.x * blockDim.x + threadIdx.x) >> 5;
    int nwarps = (gridDim.x * blockDim.x) >> 5;
    int lane   = threadIdx.x & 31;
    int n      = g_nf;

    for (int j = warp0; j < n; j += nwarps) {
        int tok = g_ftok[j];
        int v   = g_fvid[j];
        int cnt = g_counts[v];

        const float4* src = out4 + (long)tok * (DIM / 4);
        long vbase = (long)v * (DIM / 4);

        if (cnt == 1) {
#pragma unroll
            for (int i = 0; i < 4; i++) {
                int c = lane + i * 32;
                float4 x  = src[c];
                float4 wv = w4[vbase + c];
                sums4[vbase + c] = make_float4(
                    0.5f * (wv.x + x.x), 0.5f * (wv.y + x.y),
                    0.5f * (wv.z + x.z), 0.5f * (wv.w + x.w));
            }
        } else {
            float cf = (float)cnt;
#pragma unroll
            for (int i = 0; i < 4; i++) {
                int c = lane + i * 32;
                float4 x  = src[c];
                float4 wv = w4[vbase + c];
                sums4[vbase + c] = make_float4(
                    fmaf(cf, wv.x, x.x), fmaf(cf, wv.y, x.y),
                    fmaf(cf, wv.z, x.z), fmaf(cf, wv.w, x.w));
            }
        }
    }
}

// ---------------------------------------------------------------------------
// Kernel 3: atomic pass over remaining (rank>=1) tokens. Runs after the store
// pass (stream order), so the seed value is already in place.
// ---------------------------------------------------------------------------
__global__ void atomic_kernel(const float4* __restrict__ out4,
                              float* __restrict__ sums) {
    int warp0  = (blockIdx.x * blockDim.x + threadIdx.x) >> 5;
    int nwarps = (gridDim.x * blockDim.x) >> 5;
    int lane   = threadIdx.x & 31;
    int n      = g_nr;

    for (int j = warp0; j < n; j += nwarps) {
        int tok = g_rtok[j];
        int v   = g_rvid[j];
        const float4* src = out4 + (long)tok * (DIM / 4);
        float4* dst = (float4*)(sums + (long)v * DIM);
#pragma unroll
        for (int i = 0; i < 4; i++) {
            int c = lane + i * 32;
            float4 x = src[c];
            asm volatile(
                "red.global.add.v4.f32 [%0], {%1, %2, %3, %4};"
                :: "l"(dst + c), "f"(x.x), "f"(x.y), "f"(x.z), "f"(x.w)
                : "memory");
        }
    }
}

// ---------------------------------------------------------------------------
// Kernel 4: finalize (barrier-free, streaming).
//   c==0 -> out = w (copy)
//   c==1 -> already final (store pass), skip
//   c>=2 -> out = sums * (0.5/c)       (sums = c*w + Sum(x))
// Exact grid: VOCAB*DIM/4 / 256 = 50000 full blocks. Count is uniform per
// 128-thread row group, so warps never diverge on it.
// ---------------------------------------------------------------------------
__global__ void finalize_kernel(const float4* __restrict__ w4,
                                float4* __restrict__ out4) {
    long i = (long)blockIdx.x * blockDim.x + threadIdx.x;
    int row = (int)(i >> 7);            // i / 128
    int c = g_counts[row];
    if (c == 1) return;

    float4 o;
    if (c == 0) {
        o = w4[i];
    } else {
        float4 s = out4[i];
        float inv = 0.5f / (float)c;
        o = make_float4(s.x * inv, s.y * inv, s.z * inv, s.w * inv);
    }
    out4[i] = o;
}

// ---------------------------------------------------------------------------
extern "C" void kernel_launch(void* const* d_in, const int* in_sizes, int n_in,
                              void* d_out, int out_size) {
    const float* out_act   = (const float*)d_in[0];   // [S, D] f32
    const float* l2_weight = (const float*)d_in[1];   // [V, D] f32
    const int*   l2_data   = (const int*)d_in[2];     // [S] i32
    const int*   l2_idxs   = (const int*)d_in[3];     // [S] i32
    float* outp = (float*)d_out;                      // [V, D] f32

    (void)in_sizes; (void)n_in; (void)out_size;

    // 0. zero scratch
    zero_counts_kernel<<<(VOCAB + 255) / 256, 256>>>();

    // 1. compact masked tokens into (first, rest) lists + histogram
    compact_kernel<<<S_TOK / 256, 256>>>(l2_data, l2_idxs);

    // 2. store pass: designated token per touched row, plain stores
    store_kernel<<<2048, 256>>>((const float4*)out_act,
                                (const float4*)l2_weight,
                                (float4*)outp);

    // 3. atomic pass: remaining tokens
    atomic_kernel<<<1024, 256>>>((const float4*)out_act, outp);

    // 4. finalize (exact grid: 50000 blocks)
    finalize_kernel<<<(VOCAB * (DIM / 4)) / 256, 256>>>(
        (const float4*)l2_weight, (float4*)outp);
}

// round 6
// speedup vs baseline: 1.5199x; 1.1874x over previous
#include <cuda_runtime.h>

// Problem constants (from reference)
#define S_TOK 131072
#define DIM   512
#define VOCAB 100000

// Scratch (device globals — zero at module load; finalize restores zeros each
// run, so the zero-invariant holds across graph replays).
__device__ int g_counts[VOCAB];   // tokens per vocab row (final histogram)
__device__ int g_nf;              // # designated (rank-0) tokens == # touched rows
__device__ int g_nr;              // # remaining tokens (rank >= 1)
__device__ int g_ftok[S_TOK];     // designated token index per touched row
__device__ int g_fvid[S_TOK];     // its vocab id
__device__ int g_rtok[S_TOK];     // remaining tokens
__device__ int g_rvid[S_TOK];

// ---------------------------------------------------------------------------
// Kernel 1: compact masked tokens into (first, rest) lists + histogram.
// The token whose atomicAdd returns 0 is the row's designated writer.
// (g_counts / g_nf / g_nr are zero on entry.)
// ---------------------------------------------------------------------------
__global__ void compact_kernel(const int* __restrict__ l2_data,
                               const int* __restrict__ l2_idxs) {
    int i = blockIdx.x * blockDim.x + threadIdx.x;
    if (i >= S_TOK) return;
    if (l2_idxs[i] == 1) {
        int v = l2_data[i];
        int rank = atomicAdd(&g_counts[v], 1);
        if (rank == 0) {
            int pos = atomicAdd(&g_nf, 1);
            g_ftok[pos] = i;
            g_fvid[pos] = v;
        } else {
            int pos = atomicAdd(&g_nr, 1);
            g_rtok[pos] = i;
            g_rvid[pos] = v;
        }
    }
}

// ---------------------------------------------------------------------------
// Kernel 2: store pass over designated tokens. One warp per row, grid-stride.
//   c==1  -> final EMA:  out_row = 0.5*w + 0.5*x         (skipped in finalize)
//   c>=2  -> seed sums:  out_row = c*w + x               (atomics add the rest;
//            finalize scales by 0.5/c -> 0.5*w + 0.5*mean)
// Plain 16B stores, no atomics, no separate zero/init pass.
// ---------------------------------------------------------------------------
__global__ void store_kernel(const float4* __restrict__ out4,
                             const float4* __restrict__ w4,
                             float4* __restrict__ sums4) {
    int warp0  = (blockIdx.x * blockDim.x + threadIdx.x) >> 5;
    int nwarps = (gridDim.x * blockDim.x) >> 5;
    int lane   = threadIdx.x & 31;
    int n      = g_nf;

    for (int j = warp0; j < n; j += nwarps) {
        int tok = g_ftok[j];
        int v   = g_fvid[j];
        int cnt = g_counts[v];

        const float4* src = out4 + (long)tok * (DIM / 4);
        long vbase = (long)v * (DIM / 4);

        if (cnt == 1) {
#pragma unroll
            for (int i = 0; i < 4; i++) {
                int c = lane + i * 32;
                float4 x  = src[c];
                float4 wv = w4[vbase + c];
                sums4[vbase + c] = make_float4(
                    0.5f * (wv.x + x.x), 0.5f * (wv.y + x.y),
                    0.5f * (wv.z + x.z), 0.5f * (wv.w + x.w));
            }
        } else {
            float cf = (float)cnt;
#pragma unroll
            for (int i = 0; i < 4; i++) {
                int c = lane + i * 32;
                float4 x  = src[c];
                float4 wv = w4[vbase + c];
                sums4[vbase + c] = make_float4(
                    fmaf(cf, wv.x, x.x), fmaf(cf, wv.y, x.y),
                    fmaf(cf, wv.z, x.z), fmaf(cf, wv.w, x.w));
            }
        }
    }
}

// ---------------------------------------------------------------------------
// Kernel 3: atomic pass over remaining (rank>=1) tokens. Runs after the store
// pass (stream order), so the seed value is already in place.
// ---------------------------------------------------------------------------
__global__ void atomic_kernel(const float4* __restrict__ out4,
                              float* __restrict__ sums) {
    int warp0  = (blockIdx.x * blockDim.x + threadIdx.x) >> 5;
    int nwarps = (gridDim.x * blockDim.x) >> 5;
    int lane   = threadIdx.x & 31;
    int n      = g_nr;

    for (int j = warp0; j < n; j += nwarps) {
        int tok = g_rtok[j];
        int v   = g_rvid[j];
        const float4* src = out4 + (long)tok * (DIM / 4);
        float4* dst = (float4*)(sums + (long)v * DIM);
#pragma unroll
        for (int i = 0; i < 4; i++) {
            int c = lane + i * 32;
            float4 x = src[c];
            asm volatile(
                "red.global.add.v4.f32 [%0], {%1, %2, %3, %4};"
                :: "l"(dst + c), "f"(x.x), "f"(x.y), "f"(x.z), "f"(x.w)
                : "memory");
        }
    }
}

// ---------------------------------------------------------------------------
// Kernel 4: finalize + scratch reset. WARP-PER-ROW (4 float4 per thread).
//   c==0 -> out = w (copy)
//   c==1 -> already final (store pass), skip write
//   c>=2 -> out = sums * (0.5/c)       (sums = c*w + Sum(x))
// Each vocab row is owned by exactly one warp. The warp reads counts[row]
// (single lockstep LDG, all lanes same address), then lane 0 zeroes it —
// program order within the warp's single instruction stream orders the read
// before the write, and no other warp touches this row's count. No barrier.
// Grid: VOCAB/8 = 12500 blocks of 256 (8 warps/block), exact coverage.
// ---------------------------------------------------------------------------
__global__ void finalize_kernel(const float4* __restrict__ w4,
                                float4* __restrict__ out4) {
    int warp = (blockIdx.x * blockDim.x + threadIdx.x) >> 5;  // == row
    int lane = threadIdx.x & 31;
    int row  = warp;

    int c = g_counts[row];                // uniform across warp
    if (lane == 0) {
        g_counts[row] = 0;                // reset for next replay
        if (row == 0) { g_nf = 0; g_nr = 0; }
    }
    if (c == 1) return;

    long base = (long)row * (DIM / 4);
    if (c == 0) {
        float4 a = w4[base + lane];
        float4 b = w4[base + lane + 32];
        float4 d = w4[base + lane + 64];
        float4 e = w4[base + lane + 96];
        out4[base + lane]      = a;
        out4[base + lane + 32] = b;
        out4[base + lane + 64] = d;
        out4[base + lane + 96] = e;
    } else {
        float inv = 0.5f / (float)c;
        float4 a = out4[base + lane];
        float4 b = out4[base + lane + 32];
        float4 d = out4[base + lane + 64];
        float4 e = out4[base + lane + 96];
        out4[base + lane]      = make_float4(a.x*inv, a.y*inv, a.z*inv, a.w*inv);
        out4[base + lane + 32] = make_float4(b.x*inv, b.y*inv, b.z*inv, b.w*inv);
        out4[base + lane + 64] = make_float4(d.x*inv, d.y*inv, d.z*inv, d.w*inv);
        out4[base + lane + 96] = make_float4(e.x*inv, e.y*inv, e.z*inv, e.w*inv);
    }
}

// ---------------------------------------------------------------------------
extern "C" void kernel_launch(void* const* d_in, const int* in_sizes, int n_in,
                              void* d_out, int out_size) {
    const float* out_act   = (const float*)d_in[0];   // [S, D] f32
    const float* l2_weight = (const float*)d_in[1];   // [V, D] f32
    const int*   l2_data   = (const int*)d_in[2];     // [S] i32
    const int*   l2_idxs   = (const int*)d_in[3];     // [S] i32
    float* outp = (float*)d_out;                      // [V, D] f32

    (void)in_sizes; (void)n_in; (void)out_size;

    // 1. compact masked tokens into (first, rest) lists + histogram
    //    (scratch is zero: module load on first run, finalize reset after)
    compact_kernel<<<S_TOK / 256, 256>>>(l2_data, l2_idxs);

    // 2. store pass: designated token per touched row, plain stores
    store_kernel<<<2960, 256>>>((const float4*)out_act,
                                (const float4*)l2_weight,
                                (float4*)outp);

    // 3. atomic pass: remaining tokens (latency-bound -> wide grid)
    atomic_kernel<<<2368, 256>>>((const float4*)out_act, outp);

    // 4. finalize + scratch reset (warp-per-row, exact: 12500 blocks)
    finalize_kernel<<<VOCAB / 8, 256>>>((const float4*)l2_weight,
                                        (float4*)outp);
}